// round 1
// baseline (speedup 1.0000x reference)
#include <cuda_runtime.h>
#include <cstdint>

// ---------------------------------------------------------------------------
// Monarch block-diagonal butterfly linear:
//   stage1: out1[b,k,q] = sum_p x[b, k*1024+p] * w1[k,q,p]      (k=4, q=192, p=1024)
//   block transpose q=(l,b1) -> scratch[b, l, k*48+b1]
//   stage2: out[b, l*1024+s] = sum_r scratch[b,l,r] * w2[l,s,r] + bias   (r=192, s=1024)
//
// tf32 mma.sync.m16n8k8 GEMMs, CTA tile 128x64x32, 8 warps (4x2), warp 32x32.
// ---------------------------------------------------------------------------

#define BATCH   16384
#define NB      4
#define B1      48
#define INF     4096
#define OUTF    4096
#define P_DIM   1024      // stage1 K
#define Q_DIM   192       // stage1 N (= NB*B1)
#define R_DIM   192       // stage2 K
#define S_DIM   1024      // stage2 N

#define BM 128
#define BN 64
#define BK 32
#define LDK 36            // padded smem row (36 floats = 144B, 16B aligned)

static __device__ float g_scratch[(size_t)BATCH * (NB * B1 * NB)];   // [b][l][k*48+j], 48MB

__device__ __forceinline__ unsigned f2tf32(float f) {
    unsigned u;
    asm("cvt.rna.tf32.f32 %0, %1;" : "=r"(u) : "f"(f));
    return u;
}

__device__ __forceinline__ void mma_tf32(float c[4], const unsigned a[4], const unsigned b[2]) {
    asm volatile(
        "mma.sync.aligned.m16n8k8.row.col.f32.tf32.tf32.f32 "
        "{%0,%1,%2,%3}, {%4,%5,%6,%7}, {%8,%9}, {%0,%1,%2,%3};\n"
        : "+f"(c[0]), "+f"(c[1]), "+f"(c[2]), "+f"(c[3])
        : "r"(a[0]), "r"(a[1]), "r"(a[2]), "r"(a[3]), "r"(b[0]), "r"(b[1]));
}

// ---------------------------------------------------------------------------
// Stage 1:  per block bk: C[b, q] = sum_p X[b, bk*1024+p] * W1[bk, q, p]
// Epilogue scatters into g_scratch with the Monarch block transpose.
// grid: (Q_DIM/BN=3, BATCH/BM=128, NB=4), block: 256
// ---------------------------------------------------------------------------
__global__ __launch_bounds__(256) void bdb_stage1(const float* __restrict__ x,
                                                  const float* __restrict__ w1) {
    const int ntile = blockIdx.x;
    const int mtile = blockIdx.y;
    const int bk    = blockIdx.z;
    const int tid   = threadIdx.x;

    __shared__ unsigned As[BM * LDK];
    __shared__ unsigned Bs[BN * LDK];

    const float* Ag = x  + (size_t)mtile * BM * INF + (size_t)bk * P_DIM;
    const float* Bg = w1 + (size_t)bk * Q_DIM * P_DIM + (size_t)ntile * BN * P_DIM;

    const int warp = tid >> 5, lane = tid & 31;
    const int wm = warp >> 1, wn = warp & 1;       // 4 x 2 warp grid
    const int g  = lane >> 2, tg = lane & 3;

    float c[2][4][4] = {};

    for (int k0 = 0; k0 < P_DIM; k0 += BK) {
        // A tile: 128x32 = 1024 float4
        #pragma unroll
        for (int it = 0; it < 4; ++it) {
            int f = it * 256 + tid;
            int r = f >> 3, c4 = (f & 7) << 2;
            float4 v = *(const float4*)(Ag + (size_t)r * INF + k0 + c4);
            unsigned* d = &As[r * LDK + c4];
            d[0] = f2tf32(v.x); d[1] = f2tf32(v.y); d[2] = f2tf32(v.z); d[3] = f2tf32(v.w);
        }
        // B tile: 64x32 = 512 float4
        #pragma unroll
        for (int it = 0; it < 2; ++it) {
            int f = it * 256 + tid;
            int r = f >> 3, c4 = (f & 7) << 2;
            float4 v = *(const float4*)(Bg + (size_t)r * P_DIM + k0 + c4);
            unsigned* d = &Bs[r * LDK + c4];
            d[0] = f2tf32(v.x); d[1] = f2tf32(v.y); d[2] = f2tf32(v.z); d[3] = f2tf32(v.w);
        }
        __syncthreads();

        #pragma unroll
        for (int kk = 0; kk < BK; kk += 8) {
            unsigned a[2][4], b[4][2];
            #pragma unroll
            for (int mf = 0; mf < 2; ++mf) {
                int rb = wm * 32 + mf * 16 + g;
                a[mf][0] = As[rb * LDK + kk + tg];
                a[mf][1] = As[(rb + 8) * LDK + kk + tg];
                a[mf][2] = As[rb * LDK + kk + 4 + tg];
                a[mf][3] = As[(rb + 8) * LDK + kk + 4 + tg];
            }
            #pragma unroll
            for (int nf = 0; nf < 4; ++nf) {
                int nb = wn * 32 + nf * 8 + g;
                b[nf][0] = Bs[nb * LDK + kk + tg];
                b[nf][1] = Bs[nb * LDK + kk + 4 + tg];
            }
            #pragma unroll
            for (int mf = 0; mf < 2; ++mf)
                #pragma unroll
                for (int nf = 0; nf < 4; ++nf)
                    mma_tf32(c[mf][nf], a[mf], b[nf]);
        }
        __syncthreads();
    }

    // Epilogue: scatter with block transpose q=(l, j) -> scratch[row, l*192 + bk*48 + j]
    #pragma unroll
    for (int mf = 0; mf < 2; ++mf) {
        #pragma unroll
        for (int nf = 0; nf < 4; ++nf) {
            int q = ntile * BN + wn * 32 + nf * 8 + tg * 2;   // even, pair never crosses 48
            int l = q / B1;
            int j = q - l * B1;
            size_t coloff = (size_t)(l * (NB * B1) + bk * B1 + j);
            int row0 = mtile * BM + wm * 32 + mf * 16 + g;
            float* d0 = g_scratch + (size_t)row0 * (NB * B1 * NB) + coloff;
            float* d1 = d0 + (size_t)8 * (NB * B1 * NB);
            *(float2*)d0 = make_float2(c[mf][nf][0], c[mf][nf][1]);
            *(float2*)d1 = make_float2(c[mf][nf][2], c[mf][nf][3]);
        }
    }
}

// ---------------------------------------------------------------------------
// Stage 2: per block bl: out[b, bl*1024+s] = sum_r scratch[b, bl*192 + r]*W2[bl,s,r] + bias
// grid: (S_DIM/BN=16, BATCH/BM=128, NB=4), block: 256
// ---------------------------------------------------------------------------
__global__ __launch_bounds__(256) void bdb_stage2(float* __restrict__ out,
                                                  const float* __restrict__ w2,
                                                  const float* __restrict__ bias) {
    const int ntile = blockIdx.x;
    const int mtile = blockIdx.y;
    const int bl    = blockIdx.z;
    const int tid   = threadIdx.x;

    __shared__ unsigned As[BM * LDK];
    __shared__ unsigned Bs[BN * LDK];

    const int ldA = NB * B1 * NB;   // 768
    const float* Ag = g_scratch + (size_t)mtile * BM * ldA + (size_t)bl * R_DIM;
    const float* Bg = w2 + (size_t)bl * S_DIM * R_DIM + (size_t)ntile * BN * R_DIM;

    const int warp = tid >> 5, lane = tid & 31;
    const int wm = warp >> 1, wn = warp & 1;
    const int g  = lane >> 2, tg = lane & 3;

    float c[2][4][4] = {};

    for (int k0 = 0; k0 < R_DIM; k0 += BK) {   // 6 iterations
        #pragma unroll
        for (int it = 0; it < 4; ++it) {
            int f = it * 256 + tid;
            int r = f >> 3, c4 = (f & 7) << 2;
            float4 v = *(const float4*)(Ag + (size_t)r * ldA + k0 + c4);
            unsigned* d = &As[r * LDK + c4];
            d[0] = f2tf32(v.x); d[1] = f2tf32(v.y); d[2] = f2tf32(v.z); d[3] = f2tf32(v.w);
        }
        #pragma unroll
        for (int it = 0; it < 2; ++it) {
            int f = it * 256 + tid;
            int r = f >> 3, c4 = (f & 7) << 2;
            float4 v = *(const float4*)(Bg + (size_t)r * R_DIM + k0 + c4);
            unsigned* d = &Bs[r * LDK + c4];
            d[0] = f2tf32(v.x); d[1] = f2tf32(v.y); d[2] = f2tf32(v.z); d[3] = f2tf32(v.w);
        }
        __syncthreads();

        #pragma unroll
        for (int kk = 0; kk < BK; kk += 8) {
            unsigned a[2][4], b[4][2];
            #pragma unroll
            for (int mf = 0; mf < 2; ++mf) {
                int rb = wm * 32 + mf * 16 + g;
                a[mf][0] = As[rb * LDK + kk + tg];
                a[mf][1] = As[(rb + 8) * LDK + kk + tg];
                a[mf][2] = As[rb * LDK + kk + 4 + tg];
                a[mf][3] = As[(rb + 8) * LDK + kk + 4 + tg];
            }
            #pragma unroll
            for (int nf = 0; nf < 4; ++nf) {
                int nb = wn * 32 + nf * 8 + g;
                b[nf][0] = Bs[nb * LDK + kk + tg];
                b[nf][1] = Bs[nb * LDK + kk + 4 + tg];
            }
            #pragma unroll
            for (int mf = 0; mf < 2; ++mf)
                #pragma unroll
                for (int nf = 0; nf < 4; ++nf)
                    mma_tf32(c[mf][nf], a[mf], b[nf]);
        }
        __syncthreads();
    }

    // Epilogue: bias add + store
    #pragma unroll
    for (int mf = 0; mf < 2; ++mf) {
        #pragma unroll
        for (int nf = 0; nf < 4; ++nf) {
            int s = ntile * BN + wn * 32 + nf * 8 + tg * 2;
            int gcol = bl * S_DIM + s;
            float2 bb = *(const float2*)(bias + gcol);
            int row0 = mtile * BM + wm * 32 + mf * 16 + g;
            float* d0 = out + (size_t)row0 * OUTF + gcol;
            float* d1 = d0 + (size_t)8 * OUTF;
            *(float2*)d0 = make_float2(c[mf][nf][0] + bb.x, c[mf][nf][1] + bb.y);
            *(float2*)d1 = make_float2(c[mf][nf][2] + bb.x, c[mf][nf][3] + bb.y);
        }
    }
}

// ---------------------------------------------------------------------------
extern "C" void kernel_launch(void* const* d_in, const int* in_sizes, int n_in,
                              void* d_out, int out_size) {
    const float* x    = (const float*)d_in[0];
    const float* w1   = (const float*)d_in[1];
    const float* w2   = (const float*)d_in[2];
    const float* bias = (const float*)d_in[3];
    float* out = (float*)d_out;

    dim3 block(256);
    dim3 grid1(Q_DIM / BN, BATCH / BM, NB);   // (3, 128, 4)
    dim3 grid2(S_DIM / BN, BATCH / BM, NB);   // (16, 128, 4)

    bdb_stage1<<<grid1, block>>>(x, w1);
    bdb_stage2<<<grid2, block>>>(out, w2, bias);
}

// round 2
// speedup vs baseline: 1.3458x; 1.3458x over previous
#include <cuda_runtime.h>
#include <cstdint>

// ---------------------------------------------------------------------------
// Monarch block-diagonal butterfly linear (tf32 mma.m16n8k8):
//   prep:   round w1,w2 to tf32 once (tiny)
//   stage1: out1[b,k,q] = sum_p x[b,k*1024+p]*w1[k,q,p]; epilogue stores
//           tf32-rounded values with Monarch block transpose into scratch
//   stage2: out[b,l*1024+s] = sum_r scratch[b,l,r]*w2[l,s,r] + bias (no CVTs)
// cp.async 3-stage pipeline, ldmatrix.x4 fragment loads.
// ---------------------------------------------------------------------------

#define BATCH   16384
#define NB      4
#define B1      48
#define INF     4096
#define OUTF    4096
#define P_DIM   1024
#define Q_DIM   192
#define R_DIM   192
#define S_DIM   1024

#define BM 128
#define BN 64
#define BK 32
#define LDK 36                 // padded smem row: 36 floats = 144B (16B-aligned rows)
#define STAGES 3
#define ASZ (BM * LDK)         // 4608 floats
#define BSZ (BN * LDK)         // 2304 floats
#define STG (ASZ + BSZ)        // floats per stage
#define SMEM_BYTES (STAGES * STG * 4)

#define W1N (NB * Q_DIM * P_DIM)   // 786432
#define W2N (NB * S_DIM * R_DIM)   // 786432
#define LDSCR (NB * B1 * NB)       // 768

static __device__ float g_scratch[(size_t)BATCH * LDSCR];  // 48MB
static __device__ float g_w1t[W1N];
static __device__ float g_w2t[W2N];

__device__ __forceinline__ unsigned f2tf32(float f) {
    unsigned u;
    asm("cvt.rna.tf32.f32 %0, %1;" : "=r"(u) : "f"(f));
    return u;
}

__device__ __forceinline__ void mma_tf32(float c[4], const unsigned a[4], const unsigned b[2]) {
    asm volatile(
        "mma.sync.aligned.m16n8k8.row.col.f32.tf32.tf32.f32 "
        "{%0,%1,%2,%3}, {%4,%5,%6,%7}, {%8,%9}, {%0,%1,%2,%3};\n"
        : "+f"(c[0]), "+f"(c[1]), "+f"(c[2]), "+f"(c[3])
        : "r"(a[0]), "r"(a[1]), "r"(a[2]), "r"(a[3]), "r"(b[0]), "r"(b[1]));
}

__device__ __forceinline__ void ldsm4(unsigned r[4], unsigned saddr) {
    asm volatile("ldmatrix.sync.aligned.m8n8.x4.shared.b16 {%0,%1,%2,%3}, [%4];\n"
                 : "=r"(r[0]), "=r"(r[1]), "=r"(r[2]), "=r"(r[3]) : "r"(saddr));
}

__device__ __forceinline__ void cp16(void* s, const void* g) {
    unsigned sa = (unsigned)__cvta_generic_to_shared(s);
    asm volatile("cp.async.cg.shared.global [%0], [%1], 16;\n" :: "r"(sa), "l"(g));
}
__device__ __forceinline__ void cp_commit() { asm volatile("cp.async.commit_group;\n"); }
template<int N> __device__ __forceinline__ void cp_wait() {
    asm volatile("cp.async.wait_group %0;\n" :: "n"(N));
}

// ---------------------------------------------------------------------------
__global__ __launch_bounds__(256) void bdb_prep(const float* __restrict__ w1,
                                                const float* __restrict__ w2) {
    int i = blockIdx.x * 256 + threadIdx.x;
    if (i < W1N) g_w1t[i] = __uint_as_float(f2tf32(w1[i]));
    if (i < W2N) g_w2t[i] = __uint_as_float(f2tf32(w2[i]));
}

// ---------------------------------------------------------------------------
// Stage 1: grid (3, 128, 4), block 256. A = x (needs CVT), B = g_w1t (tf32).
// ---------------------------------------------------------------------------
__global__ __launch_bounds__(256, 2) void bdb_stage1(const float* __restrict__ x) {
    extern __shared__ float smem[];
    const int ntile = blockIdx.x, mtile = blockIdx.y, bk = blockIdx.z;
    const int tid = threadIdx.x;

    const float* Ag = x      + (size_t)mtile * BM * INF + (size_t)bk * P_DIM;
    const float* Bg = g_w1t  + (size_t)bk * Q_DIM * P_DIM + (size_t)ntile * BN * P_DIM;

    const int warp = tid >> 5, lane = tid & 31;
    const int wm = warp >> 1, wn = warp & 1;
    const int g = lane >> 2, tg = lane & 3;

    // ldmatrix per-thread base addresses (stage 0, kk=0), bytes
    unsigned a_addr[2], b_addr[2];
    {
        int rsel = (lane & 7) + ((lane >> 3) & 1) * 8;
        int csel = ((lane >> 4) & 1) * 4;
        #pragma unroll
        for (int mf = 0; mf < 2; ++mf)
            a_addr[mf] = (unsigned)__cvta_generic_to_shared(
                &smem[(wm * 32 + mf * 16 + rsel) * LDK + csel]);
        int rselB = (lane & 7) + ((lane >> 4) & 1) * 8;
        int cselB = ((lane >> 3) & 1) * 4;
        #pragma unroll
        for (int p = 0; p < 2; ++p)
            b_addr[p] = (unsigned)__cvta_generic_to_shared(
                &smem[ASZ + (wn * 32 + p * 16 + rselB) * LDK + cselB]);
    }

    float c[2][4][4] = {};
    const int NIT = P_DIM / BK;   // 32

    // loader lambda
    auto issue = [&](int s, int k0) {
        float* As = smem + s * STG;
        float* Bs = As + ASZ;
        #pragma unroll
        for (int it = 0; it < 4; ++it) {
            int f = it * 256 + tid, r = f >> 3, c4 = (f & 7) << 2;
            cp16(As + r * LDK + c4, Ag + (size_t)r * INF + k0 + c4);
        }
        #pragma unroll
        for (int it = 0; it < 2; ++it) {
            int f = it * 256 + tid, r = f >> 3, c4 = (f & 7) << 2;
            cp16(Bs + r * LDK + c4, Bg + (size_t)r * P_DIM + k0 + c4);
        }
    };

    issue(0, 0); cp_commit();
    issue(1, BK); cp_commit();

    for (int it = 0; it < NIT; ++it) {
        cp_wait<1>();
        __syncthreads();
        if (it + 2 < NIT) issue((it + 2) % STAGES, (it + 2) * BK);
        cp_commit();

        unsigned sb = (unsigned)((it % STAGES) * STG * 4);
        #pragma unroll
        for (int kk = 0; kk < BK; kk += 8) {
            unsigned off = sb + kk * 4;
            unsigned ar[2][4], br[2][4];
            ldsm4(ar[0], a_addr[0] + off);
            ldsm4(ar[1], a_addr[1] + off);
            ldsm4(br[0], b_addr[0] + off);
            ldsm4(br[1], b_addr[1] + off);
            #pragma unroll
            for (int i = 0; i < 4; ++i) {
                ar[0][i] = f2tf32(__uint_as_float(ar[0][i]));
                ar[1][i] = f2tf32(__uint_as_float(ar[1][i]));
            }
            #pragma unroll
            for (int mf = 0; mf < 2; ++mf) {
                mma_tf32(c[mf][0], ar[mf], &br[0][0]);
                mma_tf32(c[mf][1], ar[mf], &br[0][2]);
                mma_tf32(c[mf][2], ar[mf], &br[1][0]);
                mma_tf32(c[mf][3], ar[mf], &br[1][2]);
            }
        }
    }

    // Epilogue: tf32-round + block-transpose scatter into scratch
    #pragma unroll
    for (int mf = 0; mf < 2; ++mf) {
        #pragma unroll
        for (int nf = 0; nf < 4; ++nf) {
            int q = ntile * BN + wn * 32 + nf * 8 + tg * 2;   // even; pair stays in one 48-block
            int l = q / B1;
            int j = q - l * B1;
            size_t coloff = (size_t)(l * (NB * B1) + bk * B1 + j);
            int row0 = mtile * BM + wm * 32 + mf * 16 + g;
            float* d0 = g_scratch + (size_t)row0 * LDSCR + coloff;
            float* d1 = d0 + (size_t)8 * LDSCR;
            *(float2*)d0 = make_float2(__uint_as_float(f2tf32(c[mf][nf][0])),
                                       __uint_as_float(f2tf32(c[mf][nf][1])));
            *(float2*)d1 = make_float2(__uint_as_float(f2tf32(c[mf][nf][2])),
                                       __uint_as_float(f2tf32(c[mf][nf][3])));
        }
    }
}

// ---------------------------------------------------------------------------
// Stage 2: grid (16, 128, 4), block 256. A = scratch (tf32), B = g_w2t (tf32).
// No CVTs anywhere in the hot path.
// ---------------------------------------------------------------------------
__global__ __launch_bounds__(256, 2) void bdb_stage2(float* __restrict__ out,
                                                     const float* __restrict__ bias) {
    extern __shared__ float smem[];
    const int ntile = blockIdx.x, mtile = blockIdx.y, bl = blockIdx.z;
    const int tid = threadIdx.x;

    const float* Ag = g_scratch + (size_t)mtile * BM * LDSCR + (size_t)bl * R_DIM;
    const float* Bg = g_w2t + (size_t)bl * S_DIM * R_DIM + (size_t)ntile * BN * R_DIM;

    const int warp = tid >> 5, lane = tid & 31;
    const int wm = warp >> 1, wn = warp & 1;
    const int g = lane >> 2, tg = lane & 3;

    unsigned a_addr[2], b_addr[2];
    {
        int rsel = (lane & 7) + ((lane >> 3) & 1) * 8;
        int csel = ((lane >> 4) & 1) * 4;
        #pragma unroll
        for (int mf = 0; mf < 2; ++mf)
            a_addr[mf] = (unsigned)__cvta_generic_to_shared(
                &smem[(wm * 32 + mf * 16 + rsel) * LDK + csel]);
        int rselB = (lane & 7) + ((lane >> 4) & 1) * 8;
        int cselB = ((lane >> 3) & 1) * 4;
        #pragma unroll
        for (int p = 0; p < 2; ++p)
            b_addr[p] = (unsigned)__cvta_generic_to_shared(
                &smem[ASZ + (wn * 32 + p * 16 + rselB) * LDK + cselB]);
    }

    float c[2][4][4] = {};
    const int NIT = R_DIM / BK;   // 6

    auto issue = [&](int s, int k0) {
        float* As = smem + s * STG;
        float* Bs = As + ASZ;
        #pragma unroll
        for (int it = 0; it < 4; ++it) {
            int f = it * 256 + tid, r = f >> 3, c4 = (f & 7) << 2;
            cp16(As + r * LDK + c4, Ag + (size_t)r * LDSCR + k0 + c4);
        }
        #pragma unroll
        for (int it = 0; it < 2; ++it) {
            int f = it * 256 + tid, r = f >> 3, c4 = (f & 7) << 2;
            cp16(Bs + r * LDK + c4, Bg + (size_t)r * R_DIM + k0 + c4);
        }
    };

    issue(0, 0); cp_commit();
    issue(1, BK); cp_commit();

    for (int it = 0; it < NIT; ++it) {
        cp_wait<1>();
        __syncthreads();
        if (it + 2 < NIT) issue((it + 2) % STAGES, (it + 2) * BK);
        cp_commit();

        unsigned sb = (unsigned)((it % STAGES) * STG * 4);
        #pragma unroll
        for (int kk = 0; kk < BK; kk += 8) {
            unsigned off = sb + kk * 4;
            unsigned ar[2][4], br[2][4];
            ldsm4(ar[0], a_addr[0] + off);
            ldsm4(ar[1], a_addr[1] + off);
            ldsm4(br[0], b_addr[0] + off);
            ldsm4(br[1], b_addr[1] + off);
            #pragma unroll
            for (int mf = 0; mf < 2; ++mf) {
                mma_tf32(c[mf][0], ar[mf], &br[0][0]);
                mma_tf32(c[mf][1], ar[mf], &br[0][2]);
                mma_tf32(c[mf][2], ar[mf], &br[1][0]);
                mma_tf32(c[mf][3], ar[mf], &br[1][2]);
            }
        }
    }

    // Epilogue: bias + store
    #pragma unroll
    for (int mf = 0; mf < 2; ++mf) {
        #pragma unroll
        for (int nf = 0; nf < 4; ++nf) {
            int s = ntile * BN + wn * 32 + nf * 8 + tg * 2;
            int gcol = bl * S_DIM + s;
            float2 bb = *(const float2*)(bias + gcol);
            int row0 = mtile * BM + wm * 32 + mf * 16 + g;
            float* d0 = out + (size_t)row0 * OUTF + gcol;
            float* d1 = d0 + (size_t)8 * OUTF;
            *(float2*)d0 = make_float2(c[mf][nf][0] + bb.x, c[mf][nf][1] + bb.y);
            *(float2*)d1 = make_float2(c[mf][nf][2] + bb.x, c[mf][nf][3] + bb.y);
        }
    }
}

// ---------------------------------------------------------------------------
extern "C" void kernel_launch(void* const* d_in, const int* in_sizes, int n_in,
                              void* d_out, int out_size) {
    const float* x    = (const float*)d_in[0];
    const float* w1   = (const float*)d_in[1];
    const float* w2   = (const float*)d_in[2];
    const float* bias = (const float*)d_in[3];
    float* out = (float*)d_out;

    cudaFuncSetAttribute(bdb_stage1, cudaFuncAttributeMaxDynamicSharedMemorySize, SMEM_BYTES);
    cudaFuncSetAttribute(bdb_stage2, cudaFuncAttributeMaxDynamicSharedMemorySize, SMEM_BYTES);

    dim3 block(256);
    bdb_prep<<<(W1N + 255) / 256, block>>>(w1, w2);
    dim3 grid1(Q_DIM / BN, BATCH / BM, NB);   // (3, 128, 4)
    dim3 grid2(S_DIM / BN, BATCH / BM, NB);   // (16, 128, 4)
    bdb_stage1<<<grid1, block, SMEM_BYTES>>>(x);
    bdb_stage2<<<grid2, block, SMEM_BYTES>>>(out, w2 ? bias : bias);
}